// round 1
// baseline (speedup 1.0000x reference)
#include <cuda_runtime.h>
#include <math.h>

#define N_ROWS 131072
#define HID 512
#define RED 128
#define OUTD 512
#define EPS_N 1e-3f
#define LN_EPS 1e-5f

// scratch (allocation-free: static device arrays)
__device__ float g_v2[(size_t)N_ROWS * 512];
__device__ float g_h[(size_t)N_ROWS * 512];

// ---------------- Kernel 1: GEMM1 + scalarizer epilogue ----------------
// Block: 256 threads, handles 32 v-rows = 96 A-rows (A = v viewed [3n, 512]).
// C tile [96][128] (full reduced dim), K=512 chunked by 32.
// Thread (tx,ty) 16x16 computes 6 rows (stride 16) x 8 cols (stride 16).

__global__ void __launch_bounds__(256) k1_kernel(const float* __restrict__ v,
                                                 const float* __restrict__ Wd,
                                                 const float* __restrict__ We) {
    __shared__ union {
        struct { float A[96 * 32]; float B[32 * 129]; } ld;
        float vred[96 * 128];
    } sm;

    const int tid = threadIdx.x;
    const int tx = tid & 15, ty = tid >> 4;
    const int blk = blockIdx.x;
    const float* Ablk = v + (size_t)blk * 96 * HID;

    float acc[6][8];
#pragma unroll
    for (int u = 0; u < 6; u++)
#pragma unroll
        for (int c = 0; c < 8; c++) acc[u][c] = 0.f;

    for (int k0 = 0; k0 < HID; k0 += 32) {
        __syncthreads();
        // load A chunk: 96 rows x 32 k (768 float4, 3 per thread)
#pragma unroll
        for (int t = 0; t < 3; t++) {
            int lin = tid + 256 * t;
            int m = lin >> 3, kq = lin & 7;
            float4 val = *reinterpret_cast<const float4*>(Ablk + (size_t)m * HID + k0 + kq * 4);
            float* dst = sm.ld.A + m * 32 + kq * 4;
            dst[0] = val.x; dst[1] = val.y; dst[2] = val.z; dst[3] = val.w;
        }
        // load B chunk transposed: sB[kk][j] = Wd[j][k0+kk] (1024 float4, 4 per thread)
#pragma unroll
        for (int t = 0; t < 4; t++) {
            int lin = tid + 256 * t;
            int j = lin >> 3, kq = lin & 7;
            float4 val = *reinterpret_cast<const float4*>(Wd + (size_t)j * HID + k0 + kq * 4);
            sm.ld.B[(kq * 4 + 0) * 129 + j] = val.x;
            sm.ld.B[(kq * 4 + 1) * 129 + j] = val.y;
            sm.ld.B[(kq * 4 + 2) * 129 + j] = val.z;
            sm.ld.B[(kq * 4 + 3) * 129 + j] = val.w;
        }
        __syncthreads();
#pragma unroll
        for (int kk = 0; kk < 32; kk++) {
            float a[6], b[8];
#pragma unroll
            for (int u = 0; u < 6; u++) a[u] = sm.ld.A[(ty + 16 * u) * 32 + kk];
#pragma unroll
            for (int c = 0; c < 8; c++) b[c] = sm.ld.B[kk * 129 + tx + 16 * c];
#pragma unroll
            for (int u = 0; u < 6; u++)
#pragma unroll
                for (int c = 0; c < 8; c++)
                    acc[u][c] = fmaf(a[u], b[c], acc[u][c]);
        }
    }
    __syncthreads();
    // dump C tile to smem (vred view)
#pragma unroll
    for (int u = 0; u < 6; u++)
#pragma unroll
        for (int c = 0; c < 8; c++)
            sm.vred[(ty + 16 * u) * 128 + tx + 16 * c] = acc[u][c];
    __syncthreads();

    // ---- epilogue: norms, directions, projections -> v2 ----
    const int warp = tid >> 5, lane = tid & 31;
    // W_emb[3][128] into registers: we[e][c] for k = lane + 32c
    float we[3][4];
#pragma unroll
    for (int e = 0; e < 3; e++)
#pragma unroll
        for (int c = 0; c < 4; c++)
            we[e][c] = We[e * RED + lane + 32 * c];

    for (int t = 0; t < 4; t++) {
        int r = warp + 8 * t;                       // row within block (0..31)
        size_t grow = (size_t)blk * 32 + r;
        float vr[3][4];
#pragma unroll
        for (int i = 0; i < 3; i++)
#pragma unroll
            for (int c = 0; c < 4; c++)
                vr[i][c] = sm.vred[(r * 3 + i) * 128 + lane + 32 * c];

        // directions[i][e] = sum_k vred[i][k] * We[e][k]
        float d[3][3];
#pragma unroll
        for (int i = 0; i < 3; i++)
#pragma unroll
            for (int e = 0; e < 3; e++) {
                float s = 0.f;
#pragma unroll
                for (int c = 0; c < 4; c++) s = fmaf(vr[i][c], we[e][c], s);
#pragma unroll
                for (int o = 16; o > 0; o >>= 1)
                    s += __shfl_xor_sync(0xffffffffu, s, o);
                d[i][e] = s;
            }
        float nd[3][3];
#pragma unroll
        for (int e = 0; e < 3; e++) {
            float dn = sqrtf(d[0][e] * d[0][e] + d[1][e] * d[1][e] + d[2][e] * d[2][e]);
            float inv = 1.f / (dn + EPS_N);
            nd[0][e] = d[0][e] * inv;
            nd[1][e] = d[1][e] * inv;
            nd[2][e] = d[2][e] * inv;
        }
        float* v2row = g_v2 + grow * 512;
#pragma unroll
        for (int c = 0; c < 4; c++) {
            float n = sqrtf(vr[0][c] * vr[0][c] + vr[1][c] * vr[1][c] + vr[2][c] * vr[2][c]);
            float invn = 1.f / (n + EPS_N);
            int k = lane + 32 * c;
            v2row[k] = n;
#pragma unroll
            for (int e = 0; e < 3; e++) {
                float p = vr[0][c] * nd[0][e] + vr[1][c] * nd[1][e] + vr[2][c] * nd[2][e];
                v2row[128 + e * 128 + k] = p * invn;
            }
        }
    }
}

// ---------------- Kernel 2: H = v2 @ W_lin^T + b ----------------
// 128x128 C tile, K=512 chunked by 32, 8x8 per thread (256 threads).

__global__ void __launch_bounds__(256) k2_kernel(const float* __restrict__ Wl,
                                                 const float* __restrict__ bias) {
    __shared__ float sA[128 * 32];
    __shared__ float sB[32 * 129];

    const int tid = threadIdx.x;
    const int tx = tid & 15, ty = tid >> 4;
    const size_t row0 = (size_t)blockIdx.x * 128;
    const int col0 = blockIdx.y * 128;

    float acc[8][8];
#pragma unroll
    for (int u = 0; u < 8; u++)
#pragma unroll
        for (int c = 0; c < 8; c++) acc[u][c] = 0.f;

    for (int k0 = 0; k0 < 512; k0 += 32) {
        __syncthreads();
#pragma unroll
        for (int t = 0; t < 4; t++) {
            int lin = tid + 256 * t;
            int m = lin >> 3, kq = lin & 7;
            float4 val = *reinterpret_cast<const float4*>(g_v2 + (row0 + m) * 512 + k0 + kq * 4);
            float* dst = sA + m * 32 + kq * 4;
            dst[0] = val.x; dst[1] = val.y; dst[2] = val.z; dst[3] = val.w;
        }
#pragma unroll
        for (int t = 0; t < 4; t++) {
            int lin = tid + 256 * t;
            int o = lin >> 3, kq = lin & 7;
            float4 val = *reinterpret_cast<const float4*>(Wl + (size_t)(col0 + o) * 512 + k0 + kq * 4);
            sB[(kq * 4 + 0) * 129 + o] = val.x;
            sB[(kq * 4 + 1) * 129 + o] = val.y;
            sB[(kq * 4 + 2) * 129 + o] = val.z;
            sB[(kq * 4 + 3) * 129 + o] = val.w;
        }
        __syncthreads();
#pragma unroll
        for (int kk = 0; kk < 32; kk++) {
            float a[8], b[8];
#pragma unroll
            for (int u = 0; u < 8; u++) a[u] = sA[(ty + 16 * u) * 32 + kk];
#pragma unroll
            for (int c = 0; c < 8; c++) b[c] = sB[kk * 129 + tx + 16 * c];
#pragma unroll
            for (int u = 0; u < 8; u++)
#pragma unroll
                for (int c = 0; c < 8; c++)
                    acc[u][c] = fmaf(a[u], b[c], acc[u][c]);
        }
    }
#pragma unroll
    for (int u = 0; u < 8; u++) {
        size_t row = row0 + ty + 16 * u;
#pragma unroll
        for (int c = 0; c < 8; c++) {
            int col = col0 + tx + 16 * c;
            g_h[row * 512 + col] = acc[u][c] + bias[col];
        }
    }
}

// ---------------- Kernel 3: LayerNorm + exact GELU ----------------
// One block (128 threads) per row, 4 elems per thread.

__global__ void __launch_bounds__(128) k3_kernel(const float* __restrict__ gamma,
                                                 const float* __restrict__ beta,
                                                 float* __restrict__ out) {
    __shared__ float red[8];
    const size_t row = blockIdx.x;
    const int tid = threadIdx.x;
    const int warp = tid >> 5, lane = tid & 31;
    const float* h = g_h + row * 512;

    float4 x = *reinterpret_cast<const float4*>(h + tid * 4);
    float s = x.x + x.y + x.z + x.w;
#pragma unroll
    for (int o = 16; o > 0; o >>= 1) s += __shfl_xor_sync(0xffffffffu, s, o);
    if (lane == 0) red[warp] = s;
    __syncthreads();
    float mu = (red[0] + red[1] + red[2] + red[3]) * (1.f / 512.f);

    float dx0 = x.x - mu, dx1 = x.y - mu, dx2 = x.z - mu, dx3 = x.w - mu;
    float q = dx0 * dx0 + dx1 * dx1 + dx2 * dx2 + dx3 * dx3;
#pragma unroll
    for (int o = 16; o > 0; o >>= 1) q += __shfl_xor_sync(0xffffffffu, q, o);
    if (lane == 0) red[4 + warp] = q;
    __syncthreads();
    float var = (red[4] + red[5] + red[6] + red[7]) * (1.f / 512.f);
    float rstd = rsqrtf(var + LN_EPS);

    float4 g = *reinterpret_cast<const float4*>(gamma + tid * 4);
    float4 b = *reinterpret_cast<const float4*>(beta + tid * 4);
    float y0 = dx0 * rstd * g.x + b.x;
    float y1 = dx1 * rstd * g.y + b.y;
    float y2 = dx2 * rstd * g.z + b.z;
    float y3 = dx3 * rstd * g.w + b.w;

    const float invs2 = 0.70710678118654752f;
    float4 o4;
    o4.x = y0 * 0.5f * (1.f + erff(y0 * invs2));
    o4.y = y1 * 0.5f * (1.f + erff(y1 * invs2));
    o4.z = y2 * 0.5f * (1.f + erff(y2 * invs2));
    o4.w = y3 * 0.5f * (1.f + erff(y3 * invs2));
    *reinterpret_cast<float4*>(out + row * 512 + tid * 4) = o4;
}

// ---------------- launch ----------------
extern "C" void kernel_launch(void* const* d_in, const int* in_sizes, int n_in,
                              void* d_out, int out_size) {
    const float* v     = (const float*)d_in[0];
    const float* Wd    = (const float*)d_in[1];
    const float* We    = (const float*)d_in[2];
    const float* Wl    = (const float*)d_in[3];
    const float* bl    = (const float*)d_in[4];
    const float* gamma = (const float*)d_in[5];
    const float* beta  = (const float*)d_in[6];
    float* out = (float*)d_out;

    k1_kernel<<<N_ROWS / 32, 256>>>(v, Wd, We);
    dim3 g2(N_ROWS / 128, 4);
    k2_kernel<<<g2, 256>>>(Wl, bl);
    k3_kernel<<<N_ROWS, 128>>>(gamma, beta, out);
}